// round 16
// baseline (speedup 1.0000x reference)
#include <cuda_runtime.h>
#include <cuda_fp16.h>
#include <stdint.h>

typedef __half f16;

#define S_LEN 512
#define BATCH 128
#define IDIM  1024
#define HDIM  1024
#define KDIM  2048       // packed Whh at k offset IDIM in g_W
#define N3    3072       // 3 gates * H, interleaved col = 3*j + gate
#define MTOT  (S_LEN*BATCH)

#define TN_S  48               // per-CTA N tile
#define NBLK_S (N3/TN_S)       // 64

// ---- persistent kernel layout (KT=64 / ASTR=72, warp-private A) ----
#define NSTG   3
#define KTP    64
#define ASTRP  72
#define NKTP   (HDIM/KTP)                  // 16
#define APAIR  (16*ASTRP)                  // 1152 f16 per warp stage
#define APBLK  (NSTG*APAIR)                // 3456 f16 per warp
#define W_OFF  (8*APBLK)                   // 27648 f16
#define W_CH   (TN_S*ASTRP)                // 3456 f16 per k-chunk
#define BIAS_OFF (W_OFF + NKTP*W_CH)       // 82944 f16
#define SCGI_OFF (BIAS_OFF*2 + 256)        // bytes: after 64-float bias table
#define SC_PAIR  (16*49)                   // 784 floats per warp
#define SMEM_P   (SCGI_OFF + 8*SC_PAIR*4)  // 165888+256+25088 = 191232 B

// ---------------- device scratch ----------------
__device__ f16   g_x[(size_t)MTOT*IDIM];
__device__ f16   g_W[(size_t)2*N3*KDIM];      // Whh at [dir][n][IDIM + k]
__device__ uint4 g_wfrag[(size_t)2*NBLK_S*6144];   // Wih in MMA-fragment order
__device__ float g_bias[2][4][HDIM];          // br, bz, b_in, b_hn
__device__ f16   g_hf[2*2*BATCH*HDIM];        // [parity][dir][b][j]
__device__ unsigned g_bar2[2];                // per-dir barrier counters

// ---------------- helpers ----------------
__device__ __forceinline__ void cp16(f16* dst, const f16* src) {
    unsigned d = (unsigned)__cvta_generic_to_shared(dst);
    asm volatile("cp.async.cg.shared.global [%0], [%1], 16;\n" :: "r"(d), "l"(src));
}
__device__ __forceinline__ uint32_t smaddr(const void* p) {
    return (uint32_t)__cvta_generic_to_shared(p);
}
__device__ __forceinline__ void ldsm_x4(uint32_t r[4], uint32_t a) {
    asm volatile("ldmatrix.sync.aligned.m8n8.x4.shared.b16 {%0,%1,%2,%3},[%4];"
                 : "=r"(r[0]), "=r"(r[1]), "=r"(r[2]), "=r"(r[3]) : "r"(a));
}
// fp16-accumulator HMMA: D,C in 2 regs (half2 x2)
__device__ __forceinline__ void mma16816_h(uint32_t c[2], const uint32_t a[4],
                                           uint32_t b0, uint32_t b1) {
    asm volatile(
        "mma.sync.aligned.m16n8k16.row.col.f16.f16.f16.f16 "
        "{%0,%1},{%2,%3,%4,%5},{%6,%7},{%0,%1};"
        : "+r"(c[0]), "+r"(c[1])
        : "r"(a[0]), "r"(a[1]), "r"(a[2]), "r"(a[3]), "r"(b0), "r"(b1));
}
// promote fp16 block accumulator into fp32 accumulators
__device__ __forceinline__ void promote(float acc[4], const uint32_t c[2]) {
    float2 f0 = __half22float2(*(const __half2*)&c[0]);
    float2 f1 = __half22float2(*(const __half2*)&c[1]);
    acc[0] += f0.x; acc[1] += f0.y; acc[2] += f1.x; acc[3] += f1.y;
}
__device__ __forceinline__ float fsig(float x) {
    return __fdividef(1.f, 1.f + __expf(-x));
}
__device__ __forceinline__ float ftanh(float x) {
    return 1.f - __fdividef(2.f, __expf(2.f * x) + 1.f);
}

#define CP_COMMIT() asm volatile("cp.async.commit_group;")

// ---------------- prep kernels ----------------
__global__ void pack_x_kernel(const float* __restrict__ x) {
    int i = blockIdx.x * 256 + threadIdx.x;
    g_x[i] = __float2half_rn(x[i]);
}

__global__ void pack_whh_kernel(const float* __restrict__ Whh_f, const float* __restrict__ Whh_b) {
    int idx = blockIdx.x * 256 + threadIdx.x;   // over 2*N3*HDIM
    int k   = idx & 1023;
    int n   = (idx >> 10) % N3;
    int dir = idx / (N3 * 1024);
    int j = n / 3, g = n % 3;
    const float* W = dir ? Whh_b : Whh_f;
    g_W[((size_t)dir * N3 + n) * KDIM + IDIM + k] =
        __float2half_rn(W[(g * HDIM + j) * HDIM + k]);
}

__global__ void pack_wfrag_kernel(const float* __restrict__ Wih_f, const float* __restrict__ Wih_b) {
    int idx = blockIdx.x * 256 + threadIdx.x;   // over 3145728 u32
    int word = idx & 3;
    int lane = (idx >> 2) & 31;
    int v    = idx >> 7;
    int g2   = v % 12;
    int kt   = (v / 12) % 16;
    int nblk = (v / 192) % 64;
    int dir  = v / 12288;
    int nt = g2 >> 1, call = g2 & 1;
    int n = nblk * 48 + nt * 8 + (lane >> 2);
    int k = kt * 64 + call * 32 + word * 8 + (lane & 3) * 2;
    int srow = (n % 3) * HDIM + n / 3;
    const float* W = dir ? Wih_b : Wih_f;
    __half2 h2 = __halves2half2(__float2half_rn(W[(size_t)srow * IDIM + k]),
                                __float2half_rn(W[(size_t)srow * IDIM + k + 1]));
    ((uint32_t*)g_wfrag)[idx] = *(uint32_t*)&h2;
}

__global__ void pack_bias_kernel(const float* __restrict__ bih_f, const float* __restrict__ bhh_f,
                                 const float* __restrict__ bih_b, const float* __restrict__ bhh_b) {
    int i = blockIdx.x * 256 + threadIdx.x;   // 0..2047
    int dir = i >> 10, j = i & 1023;
    const float* bih = dir ? bih_b : bih_f;
    const float* bhh = dir ? bhh_b : bhh_f;
    g_bias[dir][0][j] = bih[j] + bhh[j];
    g_bias[dir][1][j] = bih[HDIM + j] + bhh[HDIM + j];
    g_bias[dir][2][j] = bih[2 * HDIM + j];
    g_bias[dir][3][j] = bhh[2 * HDIM + j];
}

__global__ void init_h_kernel() {
    int i = blockIdx.x * 256 + threadIdx.x;   // 2*2*B*H
    g_hf[i] = __float2half_rn(0.f);
    if (i < 2) g_bar2[i] = 0u;
}

// warp-private gh compute over 32 K: fp16 block accumulation + fp32 promote
template<int NT>
__device__ __forceinline__ void compute_warp(f16* pA, f16* pW, int lane, float acc[NT][4]) {
    const uint32_t aoff = smaddr(pA + (lane & 15) * ASTRP + (lane >> 4) * 8);
    const uint32_t boff = smaddr(pW + (lane & 7) * ASTRP + (lane >> 3) * 8);
    uint32_t a0[4], a1[4];
    ldsm_x4(a0, aoff);
    ldsm_x4(a1, aoff + 16 * 2);
#pragma unroll
    for (int nt = 0; nt < NT; ++nt) {
        uint32_t b4[4];
        ldsm_x4(b4, boff + nt * 8 * ASTRP * 2);
        uint32_t c16[2] = {0u, 0u};
        mma16816_h(c16, a0, b4[0], b4[1]);
        mma16816_h(c16, a1, b4[2], b4[3]);
        promote(acc[nt], c16);
    }
}

// ---------------- persistent fused kernel ----------------
// grid: (NBLK_S=64, 2) = 128 CTAs, block 256 (8 independent warps).
__global__ void __launch_bounds__(256) gru_persist(float* __restrict__ out) {
    extern __shared__ char smraw[];
    f16* sm  = (f16*)smraw;
    f16* wsm = sm + W_OFF;
    float* sbias = (float*)(smraw + BIAS_OFF * 2);   // [4][16]

    const int nblk = blockIdx.x, dir = blockIdx.y;
    const int t = threadIdx.x, w = t >> 5, lane = t & 31;
    const int grp = lane >> 2, tq = lane & 3;
    f16* awarp = sm + w * APBLK;
    float* sGi = (float*)(smraw + SCGI_OFF) + w * SC_PAIR;   // 16 x 49 floats

    // ---- preload Whh tile: 16 chunks x 48 rows x 64 k ----
    for (int i = t; i < NKTP * TN_S * 8; i += 256) {
        int kt   = i / (TN_S * 8);
        int r    = i % (TN_S * 8);
        int nloc = r >> 3, kq = (r & 7) * 8;
        size_t off = ((size_t)(dir * N3 + nblk * TN_S + nloc)) * KDIM + IDIM + kt * KTP + kq;
        cp16(wsm + kt * W_CH + nloc * ASTRP + kq, g_W + off);
    }
    if (t < 64) sbias[t] = g_bias[dir][t >> 4][nblk * 16 + (t & 15)];
    CP_COMMIT();
    asm volatile("cp.async.wait_group 0;");
    __syncthreads();

    // ---- per-thread persistent state: one b, 8 consecutive j ----
    const int brl    = lane >> 1;
    const int jh     = lane & 1;
    const int brow_g = w * 16 + brl;
    const int jb     = nblk * 16 + jh * 8;
    float hreg[8];
#pragma unroll
    for (int q = 0; q < 8; q++) hreg[q] = 0.f;

    const uint4* wfp = g_wfrag + (size_t)(dir * NBLK_S + nblk) * 6144 + lane;

    // ---- gi phase: x[tf] @ Wih tile -> sGi (warp-local, fp16 block accum) ----
    auto gi_phase = [&](int tf) {
        auto copyX = [&](int kt, int buf) {
            f16* st = awarp + buf * APAIR;
#pragma unroll
            for (int i = 0; i < 4; i++) {
                int slot = lane + 32 * i;
                int rl = slot >> 3, kq = (slot & 7) * 8;
                size_t off = ((size_t)tf * BATCH + w * 16 + rl) * IDIM + kt * KTP + kq;
                cp16(st + rl * ASTRP + kq, g_x + off);
            }
        };
        float acci[6][4];
#pragma unroll
        for (int i = 0; i < 6; i++)
#pragma unroll
            for (int q = 0; q < 4; q++) acci[i][q] = 0.f;

        copyX(0, 0); CP_COMMIT();
        copyX(1, 1); CP_COMMIT();

#pragma unroll 1
        for (int kt = 0; kt < NKTP; ++kt) {
            uint4 bf[12];
#pragma unroll
            for (int g2 = 0; g2 < 12; g2++) bf[g2] = __ldg(wfp + (kt * 12 + g2) * 32);
            if (kt < NKTP - 1) asm volatile("cp.async.wait_group 1;");
            else               asm volatile("cp.async.wait_group 0;");
            __syncwarp();
            if (kt + 2 < NKTP) { copyX(kt + 2, (kt + 2) % NSTG); CP_COMMIT(); }
            f16* pA = awarp + (kt % NSTG) * APAIR;
            const uint32_t ab = smaddr(pA + (lane & 15) * ASTRP + (lane >> 4) * 8);
            uint32_t a0[4], a1[4], a2[4], a3[4];
            ldsm_x4(a0, ab);
            ldsm_x4(a1, ab + 32);
            ldsm_x4(a2, ab + 64);
            ldsm_x4(a3, ab + 96);
#pragma unroll
            for (int nt = 0; nt < 6; ++nt) {
                uint32_t c16[2] = {0u, 0u};
                mma16816_h(c16, a0, bf[nt * 2].x,     bf[nt * 2].y);
                mma16816_h(c16, a1, bf[nt * 2].z,     bf[nt * 2].w);
                mma16816_h(c16, a2, bf[nt * 2 + 1].x, bf[nt * 2 + 1].y);
                mma16816_h(c16, a3, bf[nt * 2 + 1].z, bf[nt * 2 + 1].w);
                promote(acci[nt], c16);
            }
        }
        __syncwarp();
#pragma unroll
        for (int nt = 0; nt < 6; ++nt) {
            int col = nt * 8 + tq * 2;
            sGi[grp * 49 + col]           = acci[nt][0];
            sGi[grp * 49 + col + 1]       = acci[nt][1];
            sGi[(grp + 8) * 49 + col]     = acci[nt][2];
            sGi[(grp + 8) * 49 + col + 1] = acci[nt][3];
        }
        __syncwarp();
    };

    // prologue: gi for step 0
    gi_phase(dir ? (S_LEN - 1) : 0);

#pragma unroll 1
    for (int step = 0; step < S_LEN; ++step) {
        const int rpar = step & 1, wpar = rpar ^ 1;
        const int hbase = (rpar * 2 + dir) * BATCH * HDIM;

        auto copyA = [&](int kt, int buf) {
            f16* st = awarp + buf * APAIR;
#pragma unroll
            for (int i = 0; i < 4; i++) {
                int slot = lane + 32 * i;
                int rl = slot >> 3, kq = (slot & 7) * 8;
                int off = hbase + (w * 16 + rl) * HDIM + kt * KTP + kq;
                cp16(st + rl * ASTRP + kq, g_hf + off);
            }
        };

        float acc[6][4];
#pragma unroll
        for (int i = 0; i < 6; i++)
#pragma unroll
            for (int q = 0; q < 4; q++) acc[i][q] = 0.f;

        copyA(0, 0); CP_COMMIT();
        copyA(1, 1); CP_COMMIT();

#pragma unroll 1
        for (int kt = 0; kt < NKTP; ++kt) {
            if (kt < NKTP - 1) asm volatile("cp.async.wait_group 1;");
            else               asm volatile("cp.async.wait_group 0;");
            __syncwarp();
            if (kt + 2 < NKTP) { copyA(kt + 2, (kt + 2) % NSTG); CP_COMMIT(); }
            f16* pA = awarp + (kt % NSTG) * APAIR;
            f16* pW = wsm + kt * W_CH;
            compute_warp<6>(pA, pW, lane, acc);
            compute_warp<6>(pA + 32, pW + 32, lane, acc);
        }

        // ---- warp-local epilogue: frags -> warp scratch -> gates (gi from sGi) ----
        float* sC = (float*)awarp;
        {
#pragma unroll
            for (int nt = 0; nt < 6; ++nt) {
                int col = nt * 8 + tq * 2;
                sC[grp * 49 + col]           = acc[nt][0];
                sC[grp * 49 + col + 1]       = acc[nt][1];
                sC[(grp + 8) * 49 + col]     = acc[nt][2];
                sC[(grp + 8) * 49 + col + 1] = acc[nt][3];
            }
        }
        __syncwarp();

        const float* sRow = sC + brl * 49 + jh * 24;
        const float* sRowGi = sGi + brl * 49 + jh * 24;
#pragma unroll
        for (int q = 0; q < 8; q++) {
            int jl = jh * 8 + q;
            float gr  = sRow[q * 3]     + sRowGi[q * 3]     + sbias[jl];
            float gz  = sRow[q * 3 + 1] + sRowGi[q * 3 + 1] + sbias[16 + jl];
            float gnh = sRow[q * 3 + 2] + sbias[48 + jl];
            float gni = sRowGi[q * 3 + 2] + sbias[32 + jl];
            float r = fsig(gr);
            float z = fsig(gz);
            float n = ftanh(gni + r * gnh);
            hreg[q] = (1.f - z) * n + z * hreg[q];
        }
        __syncwarp();

        // packed h store (8 consecutive f16 = 16 B)
        {
            __half2 p0 = __halves2half2(__float2half_rn(hreg[0]), __float2half_rn(hreg[1]));
            __half2 p1 = __halves2half2(__float2half_rn(hreg[2]), __float2half_rn(hreg[3]));
            __half2 p2 = __halves2half2(__float2half_rn(hreg[4]), __float2half_rn(hreg[5]));
            __half2 p3 = __halves2half2(__float2half_rn(hreg[6]), __float2half_rn(hreg[7]));
            uint4 v;
            v.x = *(const unsigned*)&p0;
            v.y = *(const unsigned*)&p1;
            v.z = *(const unsigned*)&p2;
            v.w = *(const unsigned*)&p3;
            *(uint4*)(g_hf + ((wpar * 2 + dir) * BATCH + brow_g) * HDIM + jb) = v;
        }

        __syncthreads();
        if (step < S_LEN - 1 && t == 0) {
            __threadfence();
            atomicAdd(&g_bar2[dir], 1u);
        }

        // out store (2x float4)
        {
            float* op = out + ((size_t)step * BATCH + brow_g) * (2 * HDIM) + dir * HDIM + jb;
            *(float4*)op       = make_float4(hreg[0], hreg[1], hreg[2], hreg[3]);
            *(float4*)(op + 4) = make_float4(hreg[4], hreg[5], hreg[6], hreg[7]);
        }

        if (step < S_LEN - 1) {
            // gi for the NEXT step — overlaps the barrier wait
            const int s2 = step + 1;
            gi_phase(dir ? (S_LEN - 1 - s2) : s2);

            if (t == 0) {
                unsigned target = (unsigned)NBLK_S * (unsigned)(step + 1);
                while (*(volatile unsigned*)&g_bar2[dir] < target) __nanosleep(32);
                __threadfence();
            }
            __syncthreads();
        }
    }
}

// ---------------- launch ----------------
extern "C" void kernel_launch(void* const* d_in, const int* in_sizes, int n_in,
                              void* d_out, int out_size) {
    const float* x     = (const float*)d_in[0];
    const float* Wih_f = (const float*)d_in[1];
    const float* Whh_f = (const float*)d_in[2];
    const float* bih_f = (const float*)d_in[3];
    const float* bhh_f = (const float*)d_in[4];
    const float* Wih_b = (const float*)d_in[5];
    const float* Whh_b = (const float*)d_in[6];
    const float* bih_b = (const float*)d_in[7];
    const float* bhh_b = (const float*)d_in[8];
    float* out = (float*)d_out;

    cudaFuncSetAttribute(gru_persist, cudaFuncAttributeMaxDynamicSharedMemorySize, SMEM_P);

    pack_x_kernel<<<(int)((size_t)MTOT * IDIM / 256), 256>>>(x);
    pack_whh_kernel<<<2 * N3 * HDIM / 256, 256>>>(Whh_f, Whh_b);
    pack_wfrag_kernel<<<2 * NBLK_S * 6144 * 4 / 256, 256>>>(Wih_f, Wih_b);
    pack_bias_kernel<<<8, 256>>>(bih_f, bhh_f, bih_b, bhh_b);
    init_h_kernel<<<2 * 2 * BATCH * HDIM / 256, 256>>>();

    gru_persist<<<dim3(NBLK_S, 2), 256, SMEM_P>>>(out);
}